// round 5
// baseline (speedup 1.0000x reference)
#include <cuda_runtime.h>
#include <cuda_bf16.h>

namespace {

constexpr int B = 4096;
constexpr int C = 256;
constexpr int R = 4;   // batch rows per thread

// Closed-form Pauli expansion of the NQ=4, L=2 BasicEntanglerLayers circuit.
// U = E * RX(w1) * E * RX(x + w0) on |0000>, E = CNOT ring (0,1)(1,2)(2,3)(3,0).
// launch_bounds(256, 8): cap regs at 32 so all 1024 blocks are resident in one
// wave (8 blocks/SM). Stores issued per-row immediately to keep live set small.
__global__ void __launch_bounds__(256, 8)
qlin(const float* __restrict__ x, const float* __restrict__ w,
     float* __restrict__ out) {
  const int c  = threadIdx.x;          // circuit
  const int b0 = blockIdx.x * R;       // first batch row of this thread

  // Front-batched independent DRAM loads (MLP = R).
  float4 xr[R];
#pragma unroll
  for (int r = 0; r < R; ++r)
    xr[r] = *reinterpret_cast<const float4*>(x + (size_t)(b0 + r) * (C * 4) + c * 4);

  const float4 w0 = *reinterpret_cast<const float4*>(w + c * 8);      // L2-hot
  const float4 w1 = *reinterpret_cast<const float4*>(w + c * 8 + 4);

  // Per-circuit (weight-only) trig — amortized over R rows.
  float s0, c0, s1, c1, s2, c2, s3, c3;
  __sincosf(w1.x, &s0, &c0);
  __sincosf(w1.y, &s1, &c1);
  __sincosf(w1.z, &s2, &c2);
  __sincosf(w1.w, &s3, &c3);

  const float A = c0 * c1, Bv = s0 * s1, P = c0 * s1, Q = s0 * c1;
  const float D = c1 * c2, E = s1 * s2, F = c2 * c3, G = s2 * s3;

#pragma unroll
  for (int r = 0; r < R; ++r) {
    // Data trig: phi_q = x_q + w0_q (embedding RX fused with layer-1 RX).
    float S0, C0, S1, C1, S2, C2, S3, C3;
    __sincosf(xr[r].x + w0.x, &S0, &C0);
    __sincosf(xr[r].y + w0.y, &S1, &C1);
    __sincosf(xr[r].z + w0.z, &S2, &C2);
    __sincosf(xr[r].w + w0.w, &S3, &C3);

    const float C02 = C0 * C2, S02 = S0 * S2;
    const float SC  = S0 * C2, CS  = C0 * S2;
    const float C13 = C1 * C3, S13 = S1 * S3;

    const float u = fmaf(A, C02, Bv * S02);
    const float v = fmaf(P, SC, Q * CS);
    const float Z1 = C3 * u;
    const float Z3 = fmaf(F, u, G * v);

    const float t1 = fmaf(c3, C0 * C13, s3 * (S0 * S13));
    const float t2 = fmaf(c3, C0 * S13, s3 * (S0 * C13));
    const float Z0 = fmaf(D, t1, E * t2);

    const float Z2 = c0 * fmaf(D, C13, E * S13);

    // Store immediately — keeps register live-range short (no zr[] staging).
    *reinterpret_cast<float4*>(out + (size_t)(b0 + r) * (C * 4) + c * 4) =
        make_float4(Z0, Z1, Z2, Z3);
  }
}

}  // namespace

extern "C" void kernel_launch(void* const* d_in, const int* in_sizes, int n_in,
                              void* d_out, int out_size) {
  (void)in_sizes; (void)n_in; (void)out_size;
  const float* x = reinterpret_cast<const float*>(d_in[0]);
  const float* w = reinterpret_cast<const float*>(d_in[1]);
  float* out = reinterpret_cast<float*>(d_out);
  qlin<<<B / R, C>>>(x, w, out);
}